// round 3
// baseline (speedup 1.0000x reference)
#include <cuda_runtime.h>

// Problem constants (fixed by the reference).
#define B_DIM   16384
#define T_DIM   512
#define HOR     32
#define NSTEP   (T_DIM + B_DIM - 1)   // 16895 scan steps
#define NPAD    16896                 // 132 * 128, padded for unguarded float4 I/O
#define NBLK    132                   // blocks of 128 steps (= queue depth M)

// Scratch (allocation-free rule: __device__ globals).
__device__ float g_xnorm[NPAD];
__device__ float g_levels[NPAD];
__device__ float g_sseq[NPAD];

__device__ __forceinline__ float frcp(float x) {
    float r;
    asm("rcp.approx.ftz.f32 %0, %1;" : "=f"(r) : "f"(x));
    return r;
}

// Effective time series: ts[i] = x[0,i,0] (i<512) else x[i-511, 511, 0]; pad -> 1.
__device__ __forceinline__ float load_ts(const float* __restrict__ x, int i) {
    if (i < T_DIM)  return __ldg(x + i);
    if (i < NSTEP)  return __ldg(x + (i - (T_DIM - 1)) * T_DIM + (T_DIM - 1));
    return 1.0f;
}

// ---------------------------------------------------------------------------
// Single-warp blocked scan, 132 blocks of 128 steps (= seasonality queue depth).
// Within a block all seasonal divisors are known at entry, so the level
// recurrence l_t = c_t + k*l_{t-1} (k = 1-alpha, c_t = a*y_t/s_t) is a
// constant-coefficient linear scan: Kogge-Stone over 32 lane aggregates.
//
// Critical-path tricks:
//  * per-lane geometric prefixes P_j computed BEFORE the shuffle scan
//    -> all 4 levels recovered with one parallel FMA after the exclusive scan
//  * fused denominator: s_new = d/l with d = g*y + (1-g)*s*l, so the next
//    block's c' = a*y'*l*rcp(d) needs ONE rcp on the chain (not rcp(l) then
//    rcp(s_new)); rcp(l) and rs' = l*rcp(d) = 1/s_new are off-path
//  * carry broadcast (shfl idx 31) runs in parallel with the shfl_up
//  * y gathered straight from x with a 2-block-deep prefetch (~480 cyc cover)
// ---------------------------------------------------------------------------
__global__ void __launch_bounds__(32, 1)
scan_kernel(const float* __restrict__ x,
            const float* __restrict__ alpha, const float* __restrict__ gamma,
            const float* __restrict__ init_s, const float* __restrict__ level0) {
    const unsigned FULL = 0xFFFFFFFFu;
    const int lane = threadIdx.x;
    const int t0 = lane * 4;

    const float a   = alpha[0];
    const float g   = gamma[0];
    const float k   = 1.0f - a;
    const float omg = 1.0f - g;
    const float k2 = k * k, k3 = k2 * k, k4 = k2 * k2;
    const float K0 = k4, K1 = K0 * K0, K2c = K1 * K1, K3 = K2c * K2c, K4 = K3 * K3;
    const float k128 = K4 * K4;
    float kp4 = 1.0f;                       // k^(4*lane)
    for (int i = 0; i < lane; ++i) kp4 *= k4;

    float L = level0[0];                    // level entering current block

    // y for block 0 and block 1 (issue loads first for latency).
    float y0 = load_ts(x, t0 + 0), y1 = load_ts(x, t0 + 1);
    float y2 = load_ts(x, t0 + 2), y3 = load_ts(x, t0 + 3);
    float yn0 = load_ts(x, 128 + t0 + 0), yn1 = load_ts(x, 128 + t0 + 1);
    float yn2 = load_ts(x, 128 + t0 + 2), yn3 = load_ts(x, 128 + t0 + 3);

    // Initial seasonality queue (block 0 uses init_s directly).
    float4 sv = *reinterpret_cast<const float4*>(init_s + t0);
    float rs0 = frcp(sv.x), rs1 = frcp(sv.y), rs2 = frcp(sv.z), rs3 = frcp(sv.w);
    float c0 = (a * y0) * rs0, c1 = (a * y1) * rs1;
    float c2 = (a * y2) * rs2, c3 = (a * y3) * rs3;
    float gy0 = g * y0, gy1 = g * y1, gy2 = g * y2, gy3 = g * y3;
    float os0 = omg * sv.x, os1 = omg * sv.y, os2 = omg * sv.z, os3 = omg * sv.w;
    float ayn0 = a * yn0, ayn1 = a * yn1, ayn2 = a * yn2, ayn3 = a * yn3;

    #pragma unroll 1
    for (int blk = 0; blk < NBLK; ++blk) {
        const int base = blk * 128 + t0;

        // Prefetch y for block blk+2 (consumed two iterations from now).
        float yf0 = 1.f, yf1 = 1.f, yf2 = 1.f, yf3 = 1.f;
        if (blk + 2 < NBLK) {
            yf0 = load_ts(x, base + 256 + 0);
            yf1 = load_ts(x, base + 256 + 1);
            yf2 = load_ts(x, base + 256 + 2);
            yf3 = load_ts(x, base + 256 + 3);
        }

        // Within-lane geometric prefixes of c (ready before the scan needs them).
        const float P0 = c0;
        const float P1 = fmaf(k, c0, c1);
        const float P2 = fmaf(k, P1, c2);
        const float P3 = fmaf(k, P2, c3);      // lane aggregate

        // Warp inclusive scan with geometric stage coefficients k^(4*2^d).
        float I = P3, t;
        t = __shfl_up_sync(FULL, I, 1);  if (lane >= 1)  I = fmaf(K0,  t, I);
        t = __shfl_up_sync(FULL, I, 2);  if (lane >= 2)  I = fmaf(K1,  t, I);
        t = __shfl_up_sync(FULL, I, 4);  if (lane >= 4)  I = fmaf(K2c, t, I);
        t = __shfl_up_sync(FULL, I, 8);  if (lane >= 8)  I = fmaf(K3,  t, I);
        t = __shfl_up_sync(FULL, I, 16); if (lane >= 16) I = fmaf(K4,  t, I);

        float lp = __shfl_up_sync(FULL, I, 1);     // exclusive part
        const float T = __shfl_sync(FULL, I, 31);  // block total (parallel shfl)
        if (lane == 0) lp = 0.0f;

        // Level entering this lane's 4 steps, then all 4 levels in parallel.
        const float lstart = fmaf(kp4, L, lp);
        const float l0 = fmaf(k,  lstart, P0);
        const float l1 = fmaf(k2, lstart, P1);
        const float l2 = fmaf(k3, lstart, P2);
        const float l3 = fmaf(k4, lstart, P3);
        L = fmaf(k128, L, T);                      // carry for next block (off-path)

        // Fused denominator: d = g*y + (1-g)*s*l ;  s_new = d/l ; 1/s_new = l/d.
        const float d0 = fmaf(os0, l0, gy0);
        const float d1 = fmaf(os1, l1, gy1);
        const float d2 = fmaf(os2, l2, gy2);
        const float d3 = fmaf(os3, l3, gy3);
        const float rd0 = frcp(d0), rd1 = frcp(d1), rd2 = frcp(d2), rd3 = frcp(d3);

        // Next block's c' = a*y' * l * rcp(d)   (critical chain ends at the tree).
        const float nc0 = (ayn0 * l0) * rd0;
        const float nc1 = (ayn1 * l1) * rd1;
        const float nc2 = (ayn2 * l2) * rd2;
        const float nc3 = (ayn3 * l3) * rd3;

        // Off-path: outputs and next-block state.
        const float rl0 = frcp(l0), rl1 = frcp(l1), rl2 = frcp(l2), rl3 = frcp(l3);
        const float sn0 = d0 * rl0, sn1 = d1 * rl1, sn2 = d2 * rl2, sn3 = d3 * rl3;
        const float xn0 = (y0 * rs0) * rl0;
        const float xn1 = (y1 * rs1) * rl1;
        const float xn2 = (y2 * rs2) * rl2;
        const float xn3 = (y3 * rs3) * rl3;

        *reinterpret_cast<float4*>(g_xnorm  + base) = make_float4(xn0, xn1, xn2, xn3);
        *reinterpret_cast<float4*>(g_levels + base) = make_float4(l0, l1, l2, l3);
        *reinterpret_cast<float4*>(g_sseq   + base) = make_float4(sn0, sn1, sn2, sn3);

        // Rotate state: queue lives in registers (distance-128 dependency).
        rs0 = l0 * rd0; rs1 = l1 * rd1; rs2 = l2 * rd2; rs3 = l3 * rd3;  // 1/s_new
        os0 = omg * sn0; os1 = omg * sn1; os2 = omg * sn2; os3 = omg * sn3;
        c0 = nc0; c1 = nc1; c2 = nc2; c3 = nc3;
        gy0 = g * yn0; gy1 = g * yn1; gy2 = g * yn2; gy3 = g * yn3;
        y0 = yn0; y1 = yn1; y2 = yn2; y3 = yn3;
        yn0 = yf0; yn1 = yf1; yn2 = yf2; yn3 = yf3;
        ayn0 = a * yn0; ayn1 = a * yn1; ayn2 = a * yn2; ayn3 = a * yn3;
    }
}

// ---------------------------------------------------------------------------
// Materialize outputs (pure bandwidth, ~37.5MB stores; reads are L2-resident).
//   x_out[b,t]        = x_norm[b+t]                      (float4 stores)
//   denorm[b,h,{0,1}] = (levels[b+511], s_seq[b+384+h])  (float4 stores, 2 h/thr)
// ---------------------------------------------------------------------------
__global__ void __launch_bounds__(256)
out_kernel(float* __restrict__ out) {
    const int XQUADS = (B_DIM * T_DIM) / 4;  // 2097152
    int tid = blockIdx.x * blockDim.x + threadIdx.x;
    if (tid < XQUADS) {
        int idx = tid * 4;
        int b = idx >> 9;
        int t = idx & 511;
        int s = b + t;
        float4 v = make_float4(g_xnorm[s], g_xnorm[s + 1], g_xnorm[s + 2], g_xnorm[s + 3]);
        *reinterpret_cast<float4*>(out + idx) = v;
    } else {
        int j = tid - XQUADS;                // 0 .. B*16-1, two horizons per thread
        if (j < B_DIM * (HOR / 2)) {
            int b = j >> 4;
            int h = (j & 15) * 2;
            float lvl = g_levels[b + (T_DIM - 1)];
            float sa = g_sseq[b + 384 + h];
            float sb = g_sseq[b + 384 + h + 1];
            *reinterpret_cast<float4*>(out + B_DIM * T_DIM + b * (2 * HOR) + 2 * h) =
                make_float4(lvl, sa, lvl, sb);
        }
    }
}

// ---------------------------------------------------------------------------
// Launch. Inputs (metadata order): x, alpha, gamma, init_seasonality, level.
// ---------------------------------------------------------------------------
extern "C" void kernel_launch(void* const* d_in, const int* in_sizes, int n_in,
                              void* d_out, int out_size) {
    const float* x      = (const float*)d_in[0];
    const float* alpha  = (const float*)d_in[1];
    const float* gamma  = (const float*)d_in[2];
    const float* init_s = (const float*)d_in[3];
    const float* level  = (const float*)d_in[4];
    float* out = (float*)d_out;

    scan_kernel<<<1, 32>>>(x, alpha, gamma, init_s, level);
    const int total = (B_DIM * T_DIM) / 4 + B_DIM * (HOR / 2);  // 2359296
    out_kernel<<<(total + 255) / 256, 256>>>(out);
}

// round 4
// speedup vs baseline: 1.3182x; 1.3182x over previous
#include <cuda_runtime.h>

// Problem constants (fixed by the reference).
#define B_DIM   16384
#define T_DIM   512
#define HOR     32
#define NSTEP   (T_DIM + B_DIM - 1)   // 16895 scan steps
#define NPAD    16896                 // 132 * 128, padded for unguarded float4 I/O
#define NBLK    132                   // blocks of 128 steps (= queue depth M)

// Scratch (allocation-free rule: __device__ globals).
__device__ float g_ts[NPAD];
__device__ float g_xnorm[NPAD];
__device__ float g_levels[NPAD];
__device__ float g_sseq[NPAD];

__device__ __forceinline__ float frcp(float x) {
    float r;
    asm("rcp.approx.ftz.f32 %0, %1;" : "=f"(r) : "f"(x));
    return r;
}

// ---------------------------------------------------------------------------
// Kernel 1: parallel gather of the effective series (R3 showed the single-warp
// scan cannot hide scattered DRAM latency for this; a wide kernel can).
// ts[i] = x[0,i,0] for i<512 ; x[i-511, 511, 0] otherwise. Pad slot -> 1.
// ---------------------------------------------------------------------------
__global__ void prep_kernel(const float* __restrict__ x) {
    int i = blockIdx.x * blockDim.x + threadIdx.x;
    if (i < NPAD) {
        float v;
        if (i < T_DIM)       v = __ldg(x + i);
        else if (i < NSTEP)  v = __ldg(x + (i - (T_DIM - 1)) * T_DIM + (T_DIM - 1));
        else                 v = 1.0f;  // pad
        g_ts[i] = v;
    }
}

// ---------------------------------------------------------------------------
// Kernel 2: single-warp blocked scan, 132 blocks of 128 steps (= queue depth).
// Level recurrence l_t = c_t + k*l_{t-1} (k = 1-alpha, c_t = a*y_t/s_t) is a
// constant-coefficient linear scan -> Kogge-Stone over 32 lane aggregates.
// Critical-path tricks:
//  * per-lane geometric prefixes P_j computed BEFORE the shuffle scan
//  * fused denominator: s_new = d/l with d = g*y + (1-g)*s*l, so next block's
//    c' = a*y'*l*rcp(d) needs ONE rcp on the chain; rcp(l), 1/s_new off-path
//  * y read from contiguous L2-resident g_ts, 2-block prefetch (~480cyc cover)
// ---------------------------------------------------------------------------
__global__ void __launch_bounds__(32, 1)
scan_kernel(const float* __restrict__ alpha, const float* __restrict__ gamma,
            const float* __restrict__ init_s, const float* __restrict__ level0) {
    const unsigned FULL = 0xFFFFFFFFu;
    const int lane = threadIdx.x;
    const int t0 = lane * 4;

    const float a   = alpha[0];
    const float g   = gamma[0];
    const float k   = 1.0f - a;
    const float omg = 1.0f - g;
    const float k2 = k * k, k3 = k2 * k, k4 = k2 * k2;
    const float K0 = k4, K1 = K0 * K0, K2c = K1 * K1, K3 = K2c * K2c, K4 = K3 * K3;
    const float k128 = K4 * K4;
    float kp4 = 1.0f;                       // k^(4*lane)
    for (int i = 0; i < lane; ++i) kp4 *= k4;

    float L = level0[0];                    // level entering current block

    float4 yv  = *reinterpret_cast<const float4*>(g_ts + t0);
    float4 ynv = *reinterpret_cast<const float4*>(g_ts + 128 + t0);
    float y0 = yv.x,  y1 = yv.y,  y2 = yv.z,  y3 = yv.w;
    float yn0 = ynv.x, yn1 = ynv.y, yn2 = ynv.z, yn3 = ynv.w;

    // Initial seasonality queue (block 0 uses init_s directly).
    float4 sv = *reinterpret_cast<const float4*>(init_s + t0);
    float rs0 = frcp(sv.x), rs1 = frcp(sv.y), rs2 = frcp(sv.z), rs3 = frcp(sv.w);
    float c0 = (a * y0) * rs0, c1 = (a * y1) * rs1;
    float c2 = (a * y2) * rs2, c3 = (a * y3) * rs3;
    float gy0 = g * y0, gy1 = g * y1, gy2 = g * y2, gy3 = g * y3;
    float os0 = omg * sv.x, os1 = omg * sv.y, os2 = omg * sv.z, os3 = omg * sv.w;
    float ayn0 = a * yn0, ayn1 = a * yn1, ayn2 = a * yn2, ayn3 = a * yn3;

    #pragma unroll 1
    for (int blk = 0; blk < NBLK; ++blk) {
        const int base = blk * 128 + t0;

        // Prefetch y for block blk+2 (consumed two iterations from now).
        float4 yf = make_float4(1.f, 1.f, 1.f, 1.f);
        if (blk + 2 < NBLK)
            yf = *reinterpret_cast<const float4*>(g_ts + base + 256);

        // Within-lane geometric prefixes of c (ready before the scan needs them).
        const float P0 = c0;
        const float P1 = fmaf(k, c0, c1);
        const float P2 = fmaf(k, P1, c2);
        const float P3 = fmaf(k, P2, c3);      // lane aggregate

        // Warp inclusive scan with geometric stage coefficients k^(4*2^d).
        float I = P3, t;
        t = __shfl_up_sync(FULL, I, 1);  if (lane >= 1)  I = fmaf(K0,  t, I);
        t = __shfl_up_sync(FULL, I, 2);  if (lane >= 2)  I = fmaf(K1,  t, I);
        t = __shfl_up_sync(FULL, I, 4);  if (lane >= 4)  I = fmaf(K2c, t, I);
        t = __shfl_up_sync(FULL, I, 8);  if (lane >= 8)  I = fmaf(K3,  t, I);
        t = __shfl_up_sync(FULL, I, 16); if (lane >= 16) I = fmaf(K4,  t, I);

        float lp = __shfl_up_sync(FULL, I, 1);     // exclusive part
        const float T = __shfl_sync(FULL, I, 31);  // block total (parallel shfl)
        if (lane == 0) lp = 0.0f;

        // Level entering this lane's 4 steps, then all 4 levels in parallel.
        const float lstart = fmaf(kp4, L, lp);
        const float l0 = fmaf(k,  lstart, P0);
        const float l1 = fmaf(k2, lstart, P1);
        const float l2 = fmaf(k3, lstart, P2);
        const float l3 = fmaf(k4, lstart, P3);
        L = fmaf(k128, L, T);                      // carry for next block (off-path)

        // Fused denominator: d = g*y + (1-g)*s*l ;  s_new = d/l ; 1/s_new = l/d.
        const float d0 = fmaf(os0, l0, gy0);
        const float d1 = fmaf(os1, l1, gy1);
        const float d2 = fmaf(os2, l2, gy2);
        const float d3 = fmaf(os3, l3, gy3);
        const float rd0 = frcp(d0), rd1 = frcp(d1), rd2 = frcp(d2), rd3 = frcp(d3);

        // Next block's c' = a*y' * l * rcp(d)   (critical chain ends here).
        const float nc0 = (ayn0 * l0) * rd0;
        const float nc1 = (ayn1 * l1) * rd1;
        const float nc2 = (ayn2 * l2) * rd2;
        const float nc3 = (ayn3 * l3) * rd3;

        // Off-path: outputs and next-block state.
        const float rl0 = frcp(l0), rl1 = frcp(l1), rl2 = frcp(l2), rl3 = frcp(l3);
        const float sn0 = d0 * rl0, sn1 = d1 * rl1, sn2 = d2 * rl2, sn3 = d3 * rl3;
        const float xn0 = (y0 * rs0) * rl0;
        const float xn1 = (y1 * rs1) * rl1;
        const float xn2 = (y2 * rs2) * rl2;
        const float xn3 = (y3 * rs3) * rl3;

        *reinterpret_cast<float4*>(g_xnorm  + base) = make_float4(xn0, xn1, xn2, xn3);
        *reinterpret_cast<float4*>(g_levels + base) = make_float4(l0, l1, l2, l3);
        *reinterpret_cast<float4*>(g_sseq   + base) = make_float4(sn0, sn1, sn2, sn3);

        // Rotate state: queue lives in registers (distance-128 dependency).
        rs0 = l0 * rd0; rs1 = l1 * rd1; rs2 = l2 * rd2; rs3 = l3 * rd3;  // 1/s_new
        os0 = omg * sn0; os1 = omg * sn1; os2 = omg * sn2; os3 = omg * sn3;
        c0 = nc0; c1 = nc1; c2 = nc2; c3 = nc3;
        gy0 = g * yn0; gy1 = g * yn1; gy2 = g * yn2; gy3 = g * yn3;
        y0 = yn0; y1 = yn1; y2 = yn2; y3 = yn3;
        yn0 = yf.x; yn1 = yf.y; yn2 = yf.z; yn3 = yf.w;
        ayn0 = a * yn0; ayn1 = a * yn1; ayn2 = a * yn2; ayn3 = a * yn3;
    }
}

// ---------------------------------------------------------------------------
// Kernel 3: materialize outputs. One block = 4 batch rows.
//   Threads 0-511:   x_out[b][t..t+3] = xnorm[b+t..b+t+3]. Misalignment
//                    off = b&3 is row-uniform -> two ALIGNED float4 loads +
//                    uniform-branch window select (L1 wavefronts 20 -> ~12/warp).
//   Threads 512-575: denorm[b][h] = (levels[b+511], sseq[b+384+h]), float4.
// Output fits in L2 (37.5MB < 126MB) -> LTS-bound, not HBM-bound.
// ---------------------------------------------------------------------------
__global__ void __launch_bounds__(576)
out_kernel(float* __restrict__ out) {
    const float4* __restrict__ X4 = reinterpret_cast<const float4*>(g_xnorm);
    const int tid = threadIdx.x;
    const int b0  = blockIdx.x * 4;

    if (tid < 512) {
        const int r  = tid >> 7;          // row 0..3
        const int tq = tid & 127;         // float4 index within row
        const int b  = b0 + r;
        const int off = b & 3;
        const int base4 = (b >> 2) + tq;  // (b + 4*tq) >> 2
        const float4 A = X4[base4];
        const float4 B = X4[base4 + 1];
        float4 v;
        if      (off == 0) v = A;
        else if (off == 1) v = make_float4(A.y, A.z, A.w, B.x);
        else if (off == 2) v = make_float4(A.z, A.w, B.x, B.y);
        else               v = make_float4(A.w, B.x, B.y, B.z);
        *reinterpret_cast<float4*>(out + b * T_DIM + tq * 4) = v;
    } else {
        const int j = tid - 512;          // 0..63
        const int r = j >> 4;
        const int i = j & 15;             // pair index: horizons 2i, 2i+1
        const int b = b0 + r;
        const float lvl = g_levels[b + (T_DIM - 1)];
        const float sa  = g_sseq[b + 384 + 2 * i];
        const float sb  = g_sseq[b + 385 + 2 * i];
        *reinterpret_cast<float4*>(out + B_DIM * T_DIM + b * (2 * HOR) + 4 * i) =
            make_float4(lvl, sa, lvl, sb);
    }
}

// ---------------------------------------------------------------------------
// Launch. Inputs (metadata order): x, alpha, gamma, init_seasonality, level.
// ---------------------------------------------------------------------------
extern "C" void kernel_launch(void* const* d_in, const int* in_sizes, int n_in,
                              void* d_out, int out_size) {
    const float* x      = (const float*)d_in[0];
    const float* alpha  = (const float*)d_in[1];
    const float* gamma  = (const float*)d_in[2];
    const float* init_s = (const float*)d_in[3];
    const float* level  = (const float*)d_in[4];
    float* out = (float*)d_out;

    prep_kernel<<<(NPAD + 255) / 256, 256>>>(x);
    scan_kernel<<<1, 32>>>(alpha, gamma, init_s, level);
    out_kernel<<<B_DIM / 4, 576>>>(out);
}

// round 6
// speedup vs baseline: 1.5028x; 1.1401x over previous
#include <cuda_runtime.h>

// Problem constants (fixed by the reference).
#define B_DIM   16384
#define T_DIM   512
#define HOR     32
#define NSTEP   (T_DIM + B_DIM - 1)   // 16895 scan steps
#define NPAD    16896                 // 132 * 128, padded for unguarded float4 I/O
#define NBLK    132                   // blocks of 128 steps (= queue depth M)

// Scratch (allocation-free rule: __device__ globals).
__device__ float g_ts[NPAD];
__device__ float g_xnorm[NPAD];
__device__ float g_levels[NPAD];
__device__ float g_sseq[NPAD];

__device__ __forceinline__ float frcp(float x) {
    float r;
    asm("rcp.approx.ftz.f32 %0, %1;" : "=f"(r) : "f"(x));
    return r;
}

// ---------------------------------------------------------------------------
// Kernel 1: parallel gather of the effective series.
// ts[i] = x[0,i,0] for i<512 ; x[i-511, 511, 0] otherwise. Pad slot -> 1.
// ---------------------------------------------------------------------------
__global__ void prep_kernel(const float* __restrict__ x) {
    int i = blockIdx.x * blockDim.x + threadIdx.x;
    if (i < NPAD) {
        float v;
        if (i < T_DIM)       v = __ldg(x + i);
        else if (i < NSTEP)  v = __ldg(x + (i - (T_DIM - 1)) * T_DIM + (T_DIM - 1));
        else                 v = 1.0f;  // pad
        g_ts[i] = v;
    }
}

// ---------------------------------------------------------------------------
// Kernel 2: single-warp blocked scan, 132 blocks of 128 steps (= queue depth).
// l_t = c_t + k*l_{t-1},  c_t = a*y_t/s_t,  k = 1-alpha  -> Kogge-Stone over
// 32 lane aggregates with geometric stage coefficients k^(4*2^d).
//
// Chain-shortening:
//  * carry FOLDED into scan input (lane0: A = P3 + k^4*L). Then I_j is the
//    true level at the lane's last step: l3 = I, next carry = I_31.
//  * l2, l1 recovered BACKWARD: l2=(I-c3)*rk, l1=(l2-c2)*rk (ready at +8/+16
//    vs +30 through the shfl). l0 via the exclusive-shfl path (accurate).
//  * d/rcp for slots 3,2,1 issue immediately; m_j = a*y'_j*l_j overlaps the
//    MUFU latency; only the late pair (nc0, nc1) gates the next tree.
//  * 3-deep y pipeline: LDG issued 2 full iterations before first use.
// ---------------------------------------------------------------------------
__global__ void __launch_bounds__(32, 1)
scan_kernel(const float* __restrict__ alpha, const float* __restrict__ gamma,
            const float* __restrict__ init_s, const float* __restrict__ level0) {
    const unsigned FULL = 0xFFFFFFFFu;
    const int lane = threadIdx.x;
    const int t0 = lane * 4;

    const float a   = alpha[0];
    const float g   = gamma[0];
    const float k   = 1.0f - a;
    const float omg = 1.0f - g;
    const float k2 = k * k, k4 = k2 * k2;
    const float rk = 1.0f / k;                 // one-time precise divide
    const float K0 = k4, K1 = K0 * K0, K2c = K1 * K1, K3 = K2c * K2c, K4 = K3 * K3;

    float Tc = level0[0];                      // carry = level entering block

    // y pipeline: current / next / next-next.
    float4 yv  = *reinterpret_cast<const float4*>(g_ts + t0);
    float4 ynv = *reinterpret_cast<const float4*>(g_ts + 128 + t0);
    float4 ynn = *reinterpret_cast<const float4*>(g_ts + 256 + t0);
    float y0 = yv.x,  y1 = yv.y,  y2 = yv.z,  y3 = yv.w;
    float yn0 = ynv.x, yn1 = ynv.y, yn2 = ynv.z, yn3 = ynv.w;

    // Initial seasonality queue (block 0 uses init_s directly).
    float4 sv = *reinterpret_cast<const float4*>(init_s + t0);
    float rs0 = frcp(sv.x), rs1 = frcp(sv.y), rs2 = frcp(sv.z), rs3 = frcp(sv.w);
    float c0 = (a * y0) * rs0, c1 = (a * y1) * rs1;
    float c2 = (a * y2) * rs2, c3 = (a * y3) * rs3;
    float gy0 = g * y0, gy1 = g * y1, gy2 = g * y2, gy3 = g * y3;
    float os0 = omg * sv.x, os1 = omg * sv.y, os2 = omg * sv.z, os3 = omg * sv.w;
    float ayn0 = a * yn0, ayn1 = a * yn1, ayn2 = a * yn2, ayn3 = a * yn3;

    #pragma unroll 2
    for (int blk = 0; blk < NBLK; ++blk) {
        const int base = blk * 128 + t0;

        // Prefetch y for block blk+3 (consumed two iterations from now).
        float4 yf = make_float4(1.f, 1.f, 1.f, 1.f);
        if (blk + 3 < NBLK)
            yf = *reinterpret_cast<const float4*>(g_ts + base + 384);

        // Aggregate tree + carry fold (all operands early).
        const float t1raw = fmaf(k, c2, c3);
        const float t2e   = fmaf(k, c0, c1);
        const float t1    = (lane == 0) ? fmaf(k4, Tc, t1raw) : t1raw;
        float I = fmaf(k2, t2e, t1);           // scan input A (= P3 [+ k4*L])

        // Warp inclusive scan: I_j becomes the true level at step t0+3.
        float t;
        t = __shfl_up_sync(FULL, I, 1);  if (lane >= 1)  I = fmaf(K0,  t, I);
        t = __shfl_up_sync(FULL, I, 2);  if (lane >= 2)  I = fmaf(K1,  t, I);
        t = __shfl_up_sync(FULL, I, 4);  if (lane >= 4)  I = fmaf(K2c, t, I);
        t = __shfl_up_sync(FULL, I, 8);  if (lane >= 8)  I = fmaf(K3,  t, I);
        t = __shfl_up_sync(FULL, I, 16); if (lane >= 16) I = fmaf(K4,  t, I);

        // Levels: l3 free, l2/l1 backward, l0 via exclusive shfl (accurate).
        const float l3 = I;
        const float l2 = (l3 - c3) * rk;
        const float l1 = (l2 - c2) * rk;
        float lp = __shfl_up_sync(FULL, I, 1);
        if (lane == 0) lp = Tc;                // lane0's lstart is the carry
        const float l0 = fmaf(k, lp, c0);

        // d = g*y + (1-g)*s*l ; issue early slots' rcp immediately.
        const float d3 = fmaf(os3, l3, gy3);
        const float d2 = fmaf(os2, l2, gy2);
        const float d1 = fmaf(os1, l1, gy1);
        const float rd3 = frcp(d3), rd2 = frcp(d2), rd1 = frcp(d1);
        const float d0 = fmaf(os0, l0, gy0);
        const float rd0 = frcp(d0);

        // m = a*y'*l (during rcp wait), then nc = m*rd (next block's c).
        const float m3 = ayn3 * l3, m2 = ayn2 * l2;
        const float m1 = ayn1 * l1, m0 = ayn0 * l0;
        const float nc3 = m3 * rd3, nc2 = m2 * rd2;
        const float nc1 = m1 * rd1, nc0 = m0 * rd0;

        // Next carry (broadcast hides under everything downstream).
        Tc = __shfl_sync(FULL, I, 31);

        // Off-path: outputs.
        const float rl0 = frcp(l0), rl1 = frcp(l1), rl2 = frcp(l2), rl3 = frcp(l3);
        const float sn0 = d0 * rl0, sn1 = d1 * rl1, sn2 = d2 * rl2, sn3 = d3 * rl3;
        const float xn0 = (y0 * rs0) * rl0;
        const float xn1 = (y1 * rs1) * rl1;
        const float xn2 = (y2 * rs2) * rl2;
        const float xn3 = (y3 * rs3) * rl3;

        *reinterpret_cast<float4*>(g_xnorm  + base) = make_float4(xn0, xn1, xn2, xn3);
        *reinterpret_cast<float4*>(g_levels + base) = make_float4(l0, l1, l2, l3);
        *reinterpret_cast<float4*>(g_sseq   + base) = make_float4(sn0, sn1, sn2, sn3);

        // Rotate state (distance-128 queue lives in registers).
        rs0 = l0 * rd0; rs1 = l1 * rd1; rs2 = l2 * rd2; rs3 = l3 * rd3;  // 1/s_new
        os0 = omg * sn0; os1 = omg * sn1; os2 = omg * sn2; os3 = omg * sn3;
        c0 = nc0; c1 = nc1; c2 = nc2; c3 = nc3;
        gy0 = g * yn0; gy1 = g * yn1; gy2 = g * yn2; gy3 = g * yn3;
        y0 = yn0; y1 = yn1; y2 = yn2; y3 = yn3;
        yn0 = ynn.x; yn1 = ynn.y; yn2 = ynn.z; yn3 = ynn.w;
        ayn0 = a * yn0; ayn1 = a * yn1; ayn2 = a * yn2; ayn3 = a * yn3;
        ynn = yf;
    }
}

// ---------------------------------------------------------------------------
// Kernel 3: materialize outputs. One thread serves FOUR batch rows at one
// t-quad: rows 4*b4..4*b4+3 at t=4q all read the 7-float window
// xnorm[4*(b4+q) .. +6] = two ALIGNED float4 -> 4x fewer global loads than
// per-row loading; register window-select per row. Denorm part in grid tail.
// ---------------------------------------------------------------------------
#define XTASKS ((B_DIM / 4) * (T_DIM / 4))     // 524288
#define DTASKS (B_DIM * (HOR / 2))             // 262144

__global__ void __launch_bounds__(256)
out_kernel(float* __restrict__ out) {
    const float4* __restrict__ X4 = reinterpret_cast<const float4*>(g_xnorm);
    int gid = blockIdx.x * blockDim.x + threadIdx.x;
    if (gid < XTASKS) {
        const int b4 = gid >> 7;          // row group (4 rows)
        const int q  = gid & 127;         // t-quad
        const int i4 = b4 + q;
        const float4 A = X4[i4];
        const float4 B = X4[i4 + 1];
        const int rbase = (b4 * 4) * T_DIM + q * 4;
        *reinterpret_cast<float4*>(out + rbase)             = A;
        *reinterpret_cast<float4*>(out + rbase + T_DIM)     = make_float4(A.y, A.z, A.w, B.x);
        *reinterpret_cast<float4*>(out + rbase + 2 * T_DIM) = make_float4(A.z, A.w, B.x, B.y);
        *reinterpret_cast<float4*>(out + rbase + 3 * T_DIM) = make_float4(A.w, B.x, B.y, B.z);
    } else {
        const int j = gid - XTASKS;       // 0 .. DTASKS-1
        if (j < DTASKS) {
            const int b = j >> 4;
            const int i = j & 15;         // horizons 2i, 2i+1
            const float lvl = g_levels[b + (T_DIM - 1)];
            const float sa  = g_sseq[b + 384 + 2 * i];
            const float sb  = g_sseq[b + 385 + 2 * i];
            *reinterpret_cast<float4*>(out + B_DIM * T_DIM + b * (2 * HOR) + 4 * i) =
                make_float4(lvl, sa, lvl, sb);
        }
    }
}

// ---------------------------------------------------------------------------
// Launch. Inputs (metadata order): x, alpha, gamma, init_seasonality, level.
// ---------------------------------------------------------------------------
extern "C" void kernel_launch(void* const* d_in, const int* in_sizes, int n_in,
                              void* d_out, int out_size) {
    const float* x      = (const float*)d_in[0];
    const float* alpha  = (const float*)d_in[1];
    const float* gamma  = (const float*)d_in[2];
    const float* init_s = (const float*)d_in[3];
    const float* level  = (const float*)d_in[4];
    float* out = (float*)d_out;

    prep_kernel<<<NBLK, 128>>>(x);
    scan_kernel<<<1, 32>>>(alpha, gamma, init_s, level);
    out_kernel<<<(XTASKS + DTASKS) / 256, 256>>>(out);
}